// round 1
// baseline (speedup 1.0000x reference)
#include <cuda_runtime.h>
#include <math.h>

// Problem constants
#define BB 256
#define TT 512
#define HH 128
#define VV 29275
#define G3 384          // 3*H
#define MT 32           // gemm row tile

// Scratch (static device globals — no runtime allocation)
__device__ float g_G0[VV * G3];        // emb @ Wih0^T + b_ih0   (~45 MB)
__device__ float g_h0[BB * TT * HH];   // layer-0 hidden outputs (~64 MB)
__device__ float g_gx1[BB * TT * G3];  // h0 @ Wih1^T + b_ih1    (~201 MB)
__device__ float g_hlast[BB * HH];     // layer-1 final hidden

// ---------------------------------------------------------------------------
// Generic OUT[m, j] = bias[j] + sum_k A[m,k] * W[j,k],  j in [0,384), K=128
// mode 0: A = A_ext (emb),  OUT = g_G0
// mode 1: A = g_h0,         OUT = g_gx1
// ---------------------------------------------------------------------------
__global__ void __launch_bounds__(G3)
gemm384(const float* __restrict__ A_ext, const float* __restrict__ W,
        const float* __restrict__ bias, int M, int mode)
{
    __shared__ float As[MT][HH];
    const float* __restrict__ A = mode ? g_h0 : A_ext;
    float* __restrict__ OUT     = mode ? g_gx1 : g_G0;

    int j  = threadIdx.x;              // 0..383 output column
    int m0 = blockIdx.x * MT;

    // cooperative coalesced A-tile load
    for (int idx = j; idx < MT * HH; idx += G3) {
        int m = idx >> 7, k = idx & 127;
        float v = 0.0f;
        if (m0 + m < M) v = A[(m0 + m) * HH + k];
        As[m][k] = v;
    }
    __syncthreads();

    float b = bias[j];
    float acc[MT];
#pragma unroll
    for (int m = 0; m < MT; m++) acc[m] = b;

    const float4* __restrict__ Wj = reinterpret_cast<const float4*>(W + j * HH);
#pragma unroll
    for (int kg = 0; kg < HH / 4; kg++) {
        float4 w = Wj[kg];
#pragma unroll
        for (int m = 0; m < MT; m++) {
            float4 a = reinterpret_cast<const float4*>(As[m])[kg];  // broadcast LDS
            acc[m] = fmaf(w.x, a.x, acc[m]);
            acc[m] = fmaf(w.y, a.y, acc[m]);
            acc[m] = fmaf(w.z, a.z, acc[m]);
            acc[m] = fmaf(w.w, a.w, acc[m]);
        }
    }
#pragma unroll
    for (int m = 0; m < MT; m++)
        if (m0 + m < M) OUT[(m0 + m) * G3 + j] = acc[m];
}

// ---------------------------------------------------------------------------
// Persistent GRU scan. 128 CTAs, 2 batch rows each, 384 threads (1 per gate j).
// Whh in dynamic SMEM, layout [(k>>2)][j][k&3] fp32 => conflict-free LDS.128.
// layer 0: gx gathered from g_G0 via token ids; writes h to g_h0.
// layer 1: gx read from g_gx1; writes only final h to g_hlast.
// ---------------------------------------------------------------------------
__device__ __forceinline__ float sigf(float v) { return 1.0f / (1.0f + expf(-v)); }

__global__ void __launch_bounds__(G3, 1)
gru_scan(const float* __restrict__ Whh, const float* __restrict__ bhh,
         const int* __restrict__ x, int layer)
{
    extern __shared__ float Wsm[];          // 49152 floats (192 KB)
    __shared__ float hs[2][2][HH];          // double-buffered hidden state
    __shared__ float rs[2][HH];
    __shared__ float zs[2][HH];

    const float* __restrict__ gxT = layer ? g_gx1 : g_G0;
    float* __restrict__ hout      = layer ? g_hlast : g_h0;

    int j  = threadIdx.x;                   // gate index 0..383
    int b0 = blockIdx.x * 2, b1 = b0 + 1;

    // stage Whh: Wsm[((k>>2)*384 + jj)*4 + (k&3)] = Whh[jj*128 + k]
    for (int idx = j; idx < G3 * HH; idx += G3) {
        int jj = idx >> 7, k = idx & 127;
        Wsm[((k >> 2) * G3 + jj) * 4 + (k & 3)] = Whh[idx];
    }
    if (j < HH) { hs[0][0][j] = 0.0f; hs[0][1][j] = 0.0f; }
    float bh = bhh[j];
    __syncthreads();

    int buf = 0;
    for (int t = 0; t < TT; t++) {
        // input-side gate values (issued early; consumed ~1500 cyc later)
        float gxa, gxb;
        if (layer == 0) {
            gxa = gxT[x[b0 * TT + t] * G3 + j];
            gxb = gxT[x[b1 * TT + t] * G3 + j];
        } else {
            gxa = gxT[(b0 * TT + t) * G3 + j];
            gxb = gxT[(b1 * TT + t) * G3 + j];
        }

        // gh[j] = bhh[j] + sum_k Whh[j,k] * h[row][k]   (4 accumulation chains)
        float a0 = bh, a0b = 0.0f, a1 = bh, a1b = 0.0f;
        const float4* __restrict__ Wj  = reinterpret_cast<const float4*>(Wsm) + j;
        const float4* __restrict__ h0p = reinterpret_cast<const float4*>(hs[buf][0]);
        const float4* __restrict__ h1p = reinterpret_cast<const float4*>(hs[buf][1]);
#pragma unroll
        for (int kg = 0; kg < HH / 4; kg += 2) {
            float4 w  = Wj[kg * G3];
            float4 ha = h0p[kg], hb = h1p[kg];
            a0 = fmaf(w.x, ha.x, a0); a0 = fmaf(w.y, ha.y, a0);
            a0 = fmaf(w.z, ha.z, a0); a0 = fmaf(w.w, ha.w, a0);
            a1 = fmaf(w.x, hb.x, a1); a1 = fmaf(w.y, hb.y, a1);
            a1 = fmaf(w.z, hb.z, a1); a1 = fmaf(w.w, hb.w, a1);
            float4 w2  = Wj[(kg + 1) * G3];
            float4 ha2 = h0p[kg + 1], hb2 = h1p[kg + 1];
            a0b = fmaf(w2.x, ha2.x, a0b); a0b = fmaf(w2.y, ha2.y, a0b);
            a0b = fmaf(w2.z, ha2.z, a0b); a0b = fmaf(w2.w, ha2.w, a0b);
            a1b = fmaf(w2.x, hb2.x, a1b); a1b = fmaf(w2.y, hb2.y, a1b);
            a1b = fmaf(w2.z, hb2.z, a1b); a1b = fmaf(w2.w, hb2.w, a1b);
        }
        float gh0 = a0 + a0b, gh1 = a1 + a1b;

        // gates: j<128 -> r, 128..255 -> z, 256..383 -> n & update
        if (j < HH) {
            rs[0][j] = sigf(gxa + gh0);
            rs[1][j] = sigf(gxb + gh1);
        } else if (j < 2 * HH) {
            zs[0][j - HH] = sigf(gxa + gh0);
            zs[1][j - HH] = sigf(gxb + gh1);
        }
        __syncthreads();
        if (j >= 2 * HH) {
            int i = j - 2 * HH;
            float n0 = tanhf(gxa + rs[0][i] * gh0);
            float n1 = tanhf(gxb + rs[1][i] * gh1);
            float z0 = zs[0][i], z1 = zs[1][i];
            float hn0 = n0 + z0 * (hs[buf][0][i] - n0);   // (1-z)*n + z*h
            float hn1 = n1 + z1 * (hs[buf][1][i] - n1);
            hs[buf ^ 1][0][i] = hn0;
            hs[buf ^ 1][1][i] = hn1;
            if (layer == 0) {
                hout[(b0 * TT + t) * HH + i] = hn0;
                hout[(b1 * TT + t) * HH + i] = hn1;
            } else if (t == TT - 1) {
                hout[b0 * HH + i] = hn0;
                hout[b1 * HH + i] = hn1;
            }
        }
        __syncthreads();
        buf ^= 1;
    }
}

// ---------------------------------------------------------------------------
// out[b, o] = fc_b[o] + sum_k relu(hlast[b,k]) * fc_w[o,k]
// ---------------------------------------------------------------------------
__global__ void __launch_bounds__(BB)
fc_kernel(const float* __restrict__ fcw, const float* __restrict__ fcb,
          float* __restrict__ out)
{
    __shared__ float ws[3 * HH];
    int b = threadIdx.x;
    for (int i = b; i < 3 * HH; i += BB) ws[i] = fcw[i];
    __syncthreads();
    float a0 = fcb[0], a1 = fcb[1], a2 = fcb[2];
#pragma unroll 4
    for (int k = 0; k < HH; k++) {
        float h = g_hlast[b * HH + k];
        h = h > 0.0f ? h : 0.0f;
        a0 = fmaf(h, ws[k], a0);
        a1 = fmaf(h, ws[HH + k], a1);
        a2 = fmaf(h, ws[2 * HH + k], a2);
    }
    out[b * 3 + 0] = a0;
    out[b * 3 + 1] = a1;
    out[b * 3 + 2] = a2;
}

// ---------------------------------------------------------------------------
extern "C" void kernel_launch(void* const* d_in, const int* in_sizes, int n_in,
                              void* d_out, int out_size)
{
    const int*   x    = (const int*)  d_in[0];
    const float* emb  = (const float*)d_in[1];
    const float* W_ih = (const float*)d_in[2];   // [2][384][128]
    const float* W_hh = (const float*)d_in[3];   // [2][384][128]
    const float* b_ih = (const float*)d_in[4];   // [2][384]
    const float* b_hh = (const float*)d_in[5];   // [2][384]
    const float* fc_w = (const float*)d_in[6];   // [3][128]
    const float* fc_b = (const float*)d_in[7];   // [3]
    float* out = (float*)d_out;

    // 192 KB dynamic smem for the scan kernel (idempotent; ignore status)
    cudaFuncSetAttribute(gru_scan, cudaFuncAttributeMaxDynamicSharedMemorySize,
                         G3 * HH * (int)sizeof(float));

    const int smem = G3 * HH * (int)sizeof(float);

    // 1) G0 = emb @ Wih0^T + b_ih0  (vocab-side precompute: V < B*T)
    gemm384<<<(VV + MT - 1) / MT, G3>>>(emb, W_ih, b_ih, VV, 0);
    // 2) layer-0 scan (gx gathered from G0), writes g_h0
    gru_scan<<<BB / 2, G3, smem>>>(W_hh, b_hh, x, 0);
    // 3) gx1 = h0 @ Wih1^T + b_ih1
    gemm384<<<(BB * TT) / MT, G3>>>(nullptr, W_ih + G3 * HH, b_ih + G3, BB * TT, 1);
    // 4) layer-1 scan, writes g_hlast
    gru_scan<<<BB / 2, G3, smem>>>(W_hh + G3 * HH, b_hh + G3, x, 1);
    // 5) head
    fc_kernel<<<1, BB>>>(fc_w, fc_b, out);
}

// round 2
// speedup vs baseline: 1.2526x; 1.2526x over previous
#include <cuda_runtime.h>
#include <math.h>

typedef unsigned long long u64;

// Problem constants
#define BB 256
#define TT 512
#define HH 128
#define VV 29275
#define G3 384          // 3*H
#define GM 16           // gemm row tile

// Scratch (static device globals — no runtime allocation)
__device__ float g_G0[VV * G3];        // emb @ Wih0^T + b_ih0   (~45 MB)
__device__ float g_h0[BB * TT * HH];   // layer-0 hidden outputs (~64 MB)
__device__ float g_gx1[BB * TT * G3];  // h0 @ Wih1^T + b_ih1    (~201 MB)
__device__ float g_hlast[BB * HH];     // layer-1 final hidden

// ---------------------------------------------------------------------------
// f32x2 packed helpers (Blackwell packed fp32 pipe: 2 FMAs per issue slot)
// ---------------------------------------------------------------------------
__device__ __forceinline__ u64 ffma2(u64 a, u64 b, u64 c) {
    u64 d;
    asm("fma.rn.f32x2 %0, %1, %2, %3;" : "=l"(d) : "l"(a), "l"(b), "l"(c));
    return d;
}
__device__ __forceinline__ float2 unpk(u64 v) {
    float2 r;
    asm("mov.b64 {%0, %1}, %2;" : "=f"(r.x), "=f"(r.y) : "l"(v));
    return r;
}

// fast sigmoid / tanh via MUFU (ex2 + rcp); rel err ~2^-21, well inside budget
__device__ __forceinline__ float sigf(float v) {
    return __fdividef(1.0f, 1.0f + __expf(-v));
}
__device__ __forceinline__ float tanhfast(float v) {
    return fmaf(-2.0f, __fdividef(1.0f, 1.0f + __expf(2.0f * v)), 1.0f);
}

// ---------------------------------------------------------------------------
// GEMM: OUT[m, j] = bias[j] + sum_k A[m,k] * W[j,k],  j in [0,384), K=128.
// 192 threads; each thread computes 2 output columns (j, j+192) x GM rows,
// k-pair packed FFMA2, A-tile broadcast from SMEM reused across both columns.
// mode 0: A = A_ext (emb) -> g_G0 ;  mode 1: A = g_h0 -> g_gx1
// ---------------------------------------------------------------------------
__global__ void __launch_bounds__(192)
gemm384(const float* __restrict__ A_ext, const float* __restrict__ W,
        const float* __restrict__ bias, int M, int mode)
{
    __shared__ __align__(16) float As[GM][HH];
    const float* __restrict__ A = mode ? g_h0 : A_ext;
    float* __restrict__ OUT     = mode ? g_gx1 : g_G0;

    const int tid = threadIdx.x;
    const int m0  = blockIdx.x * GM;

    // stage A tile (coalesced)
    for (int idx = tid; idx < GM * HH; idx += 192) {
        int m = idx >> 7, k = idx & 127;
        float v = 0.0f;
        if (m0 + m < M) v = A[(m0 + m) * HH + k];
        As[m][k] = v;
    }
    __syncthreads();

    const int j1 = tid, j2 = tid + 192;
    u64 acc1[GM], acc2[GM];
#pragma unroll
    for (int m = 0; m < GM; m++) { acc1[m] = 0ull; acc2[m] = 0ull; }

    const ulonglong2* __restrict__ W1 = (const ulonglong2*)(W + j1 * HH);
    const ulonglong2* __restrict__ W2 = (const ulonglong2*)(W + j2 * HH);

#pragma unroll
    for (int q = 0; q < HH / 4; q++) {          // 4 k per q
        ulonglong2 w1 = W1[q];
        ulonglong2 w2 = W2[q];
#pragma unroll
        for (int m = 0; m < GM; m++) {
            ulonglong2 a = ((const ulonglong2*)As[m])[q];   // broadcast LDS.128
            acc1[m] = ffma2(w1.x, a.x, acc1[m]);
            acc1[m] = ffma2(w1.y, a.y, acc1[m]);
            acc2[m] = ffma2(w2.x, a.x, acc2[m]);
            acc2[m] = ffma2(w2.y, a.y, acc2[m]);
        }
    }

    float b1 = bias[j1], b2 = bias[j2];
#pragma unroll
    for (int m = 0; m < GM; m++) {
        if (m0 + m < M) {
            float2 s1 = unpk(acc1[m]);
            float2 s2 = unpk(acc2[m]);
            OUT[(m0 + m) * G3 + j1] = b1 + s1.x + s1.y;
            OUT[(m0 + m) * G3 + j2] = b2 + s2.x + s2.y;
        }
    }
}

// ---------------------------------------------------------------------------
// Persistent GRU scan. 128 CTAs x 384 threads, 2 batch rows per CTA.
// Thread j computes gate-row j for both batch rows.
// Whh row j: k in [0,96) register-resident (48 u64), k in [96,128) in SMEM.
// FFMA2 packs k-pairs; horizontal add at the end (no operand duplication).
// ---------------------------------------------------------------------------
__global__ void __launch_bounds__(G3, 1)
gru_scan(const float* __restrict__ Whh, const float* __restrict__ bhh,
         const int* __restrict__ x, int layer)
{
    extern __shared__ ulonglong2 Wsm2[];            // 8*384 ulonglong2 = 48 KB
    __shared__ __align__(16) float hbuf[2][2][HH];  // [buf][row][k]
    __shared__ float2 rp[HH], zp[HH];
    __shared__ int    xs[2][TT];

    const int j  = threadIdx.x;
    const int b0 = blockIdx.x * 2, b1 = b0 + 1;
    const float* __restrict__ gxT = layer ? g_gx1 : g_G0;

    // --- init: W into regs + smem, tokens into smem, h=0 ---
    u64 wreg[48];
    {
        const ulonglong2* __restrict__ Wr = (const ulonglong2*)(Whh + j * HH);
#pragma unroll
        for (int q = 0; q < 24; q++) {              // k = 0..95
            ulonglong2 w = Wr[q];
            wreg[2 * q]     = w.x;
            wreg[2 * q + 1] = w.y;
        }
#pragma unroll
        for (int q = 0; q < 8; q++)                 // k = 96..127
            Wsm2[q * G3 + j] = Wr[24 + q];
    }
    for (int i = j; i < 2 * TT; i += G3) {
        int r = i >> 9, t = i & (TT - 1);
        ((int*)xs)[i] = x[(b0 + r) * TT + t];
        (void)t;
    }
    if (j < HH) { hbuf[0][0][j] = 0.0f; hbuf[0][1][j] = 0.0f; }
    const float bh = bhh[j];
    __syncthreads();

    // preload gx for t=0
    float gxa, gxb;
    if (layer == 0) {
        gxa = __ldg(&gxT[xs[0][0] * G3 + j]);
        gxb = __ldg(&gxT[xs[1][0] * G3 + j]);
    } else {
        gxa = __ldg(&gxT[(b0 * TT) * G3 + j]);
        gxb = __ldg(&gxT[(b1 * TT) * G3 + j]);
    }

    for (int t = 0; t < TT; t++) {
        const int buf = t & 1;

        // prefetch next step's input gates (consumed after ~1 step of latency)
        float ngxa = 0.0f, ngxb = 0.0f;
        if (t + 1 < TT) {
            if (layer == 0) {
                ngxa = __ldg(&gxT[xs[0][t + 1] * G3 + j]);
                ngxb = __ldg(&gxT[xs[1][t + 1] * G3 + j]);
            } else {
                ngxa = __ldg(&gxT[(b0 * TT + t + 1) * G3 + j]);
                ngxb = __ldg(&gxT[(b1 * TT + t + 1) * G3 + j]);
            }
        }

        // gh[j] for both rows: packed k-pair dot product
        u64 a0 = 0ull, a1 = 0ull, a2 = 0ull, a3 = 0ull;
        const ulonglong2* __restrict__ h0p = (const ulonglong2*)hbuf[buf][0];
        const ulonglong2* __restrict__ h1p = (const ulonglong2*)hbuf[buf][1];
#pragma unroll
        for (int q = 0; q < 24; q++) {
            ulonglong2 ha = h0p[q];
            ulonglong2 hb = h1p[q];
            a0 = ffma2(wreg[2 * q],     ha.x, a0);
            a1 = ffma2(wreg[2 * q + 1], ha.y, a1);
            a2 = ffma2(wreg[2 * q],     hb.x, a2);
            a3 = ffma2(wreg[2 * q + 1], hb.y, a3);
        }
#pragma unroll
        for (int q = 0; q < 8; q++) {
            ulonglong2 w  = Wsm2[q * G3 + j];
            ulonglong2 ha = h0p[24 + q];
            ulonglong2 hb = h1p[24 + q];
            a0 = ffma2(w.x, ha.x, a0);
            a1 = ffma2(w.y, ha.y, a1);
            a2 = ffma2(w.x, hb.x, a2);
            a3 = ffma2(w.y, hb.y, a3);
        }
        float2 f0 = unpk(a0), f1 = unpk(a1), f2 = unpk(a2), f3 = unpk(a3);
        float gh0 = bh + ((f0.x + f0.y) + (f1.x + f1.y));
        float gh1 = bh + ((f2.x + f2.y) + (f3.x + f3.y));

        // gate split: warps 0-3 -> r, 4-7 -> z, 8-11 -> n + state update
        if (j < HH) {
            rp[j] = make_float2(sigf(gxa + gh0), sigf(gxb + gh1));
        } else if (j < 2 * HH) {
            zp[j - HH] = make_float2(sigf(gxa + gh0), sigf(gxb + gh1));
        }
        __syncthreads();
        if (j >= 2 * HH) {
            const int i = j - 2 * HH;
            float2 r = rp[i], z = zp[i];
            float n0 = tanhfast(gxa + r.x * gh0);
            float n1 = tanhfast(gxb + r.y * gh1);
            float h0o = hbuf[buf][0][i], h1o = hbuf[buf][1][i];
            float hn0 = n0 + z.x * (h0o - n0);     // (1-z)*n + z*h
            float hn1 = n1 + z.y * (h1o - n1);
            hbuf[buf ^ 1][0][i] = hn0;
            hbuf[buf ^ 1][1][i] = hn1;
            if (layer == 0) {
                g_h0[(b0 * TT + t) * HH + i] = hn0;
                g_h0[(b1 * TT + t) * HH + i] = hn1;
            } else if (t == TT - 1) {
                g_hlast[b0 * HH + i] = hn0;
                g_hlast[b1 * HH + i] = hn1;
            }
        }
        __syncthreads();
        gxa = ngxa;
        gxb = ngxb;
    }
}

// ---------------------------------------------------------------------------
// out[b, o] = fc_b[o] + sum_k relu(hlast[b,k]) * fc_w[o,k]
// ---------------------------------------------------------------------------
__global__ void __launch_bounds__(BB)
fc_kernel(const float* __restrict__ fcw, const float* __restrict__ fcb,
          float* __restrict__ out)
{
    __shared__ float ws[3 * HH];
    int b = threadIdx.x;
    for (int i = b; i < 3 * HH; i += BB) ws[i] = fcw[i];
    __syncthreads();
    float a0 = fcb[0], a1 = fcb[1], a2 = fcb[2];
#pragma unroll 4
    for (int k = 0; k < HH; k++) {
        float h = g_hlast[b * HH + k];
        h = h > 0.0f ? h : 0.0f;
        a0 = fmaf(h, ws[k], a0);
        a1 = fmaf(h, ws[HH + k], a1);
        a2 = fmaf(h, ws[2 * HH + k], a2);
    }
    out[b * 3 + 0] = a0;
    out[b * 3 + 1] = a1;
    out[b * 3 + 2] = a2;
}

// ---------------------------------------------------------------------------
extern "C" void kernel_launch(void* const* d_in, const int* in_sizes, int n_in,
                              void* d_out, int out_size)
{
    const int*   x    = (const int*)  d_in[0];
    const float* emb  = (const float*)d_in[1];
    const float* W_ih = (const float*)d_in[2];   // [2][384][128]
    const float* W_hh = (const float*)d_in[3];   // [2][384][128]
    const float* b_ih = (const float*)d_in[4];   // [2][384]
    const float* b_hh = (const float*)d_in[5];   // [2][384]
    const float* fc_w = (const float*)d_in[6];   // [3][128]
    const float* fc_b = (const float*)d_in[7];   // [3]
    float* out = (float*)d_out;

    const int smem = 8 * G3 * (int)sizeof(ulonglong2);   // 48 KB
    cudaFuncSetAttribute(gru_scan, cudaFuncAttributeMaxDynamicSharedMemorySize,
                         smem);

    // 1) G0 = emb @ Wih0^T + b_ih0  (vocab-side precompute: V < B*T)
    gemm384<<<(VV + GM - 1) / GM, 192>>>(emb, W_ih, b_ih, VV, 0);
    // 2) layer-0 scan (gx gathered from G0), writes g_h0
    gru_scan<<<BB / 2, G3, smem>>>(W_hh, b_hh, x, 0);
    // 3) gx1 = h0 @ Wih1^T + b_ih1
    gemm384<<<(BB * TT) / GM, 192>>>(nullptr, W_ih + G3 * HH, b_ih + G3, BB * TT, 1);
    // 4) layer-1 scan, writes g_hlast
    gru_scan<<<BB / 2, G3, smem>>>(W_hh + G3 * HH, b_hh + G3, x, 1);
    // 5) head
    fc_kernel<<<1, BB>>>(fc_w, fc_b, out);
}

// round 3
// speedup vs baseline: 1.4244x; 1.1371x over previous
#include <cuda_runtime.h>
#include <math.h>

typedef unsigned long long u64;

// Problem constants
#define BB 256
#define TT 512
#define HH 128
#define VV 29275
#define G3 384          // 3*H
#define GM 16           // gemm row tile
#define NCTA 148        // persistent gemm grid

// Scratch (static device globals — no runtime allocation)
__device__ float g_G0[VV * G3];        // emb @ Wih0^T + b_ih0   (~45 MB)
__device__ float g_h0[BB * TT * HH];   // layer-0 hidden outputs (~64 MB)
__device__ float g_gx1[BB * TT * G3];  // h0 @ Wih1^T + b_ih1    (~201 MB)
__device__ float g_hlast[BB * HH];     // layer-1 final hidden

// ---------------------------------------------------------------------------
// f32x2 packed helpers
// ---------------------------------------------------------------------------
__device__ __forceinline__ u64 ffma2(u64 a, u64 b, u64 c) {
    u64 d;
    asm("fma.rn.f32x2 %0, %1, %2, %3;" : "=l"(d) : "l"(a), "l"(b), "l"(c));
    return d;
}
__device__ __forceinline__ float2 unpk(u64 v) {
    float2 r;
    asm("mov.b64 {%0, %1}, %2;" : "=f"(r.x), "=f"(r.y) : "l"(v));
    return r;
}

__device__ __forceinline__ float sigf(float v) {
    return __fdividef(1.0f, 1.0f + __expf(-v));
}
__device__ __forceinline__ float tanhfast(float v) {
    return fmaf(-2.0f, __fdividef(1.0f, 1.0f + __expf(2.0f * v)), 1.0f);
}

// ---------------------------------------------------------------------------
// Persistent GEMM: OUT[m, j] = bias[j] + sum_k A[m,k] * W[j,k]
// 148 CTAs x 384 threads. Thread j holds W row j: k[0,96) in 48 u64 regs,
// k[96,128) staged once in SMEM [q][j] (conflict-free). A tiles (16 rows)
// double-buffered in SMEM, consumed via broadcast LDS.128. W gmem traffic
// is once per CTA -> no L1tex scatter in the hot loop.
// mode 0: A = A_ext (emb) -> g_G0 ;  mode 1: A = g_h0 -> g_gx1
// ---------------------------------------------------------------------------
__global__ void __launch_bounds__(G3, 1)
gemm_persist(const float* __restrict__ A_ext, const float* __restrict__ W,
             const float* __restrict__ bias, int M, int mode)
{
    extern __shared__ char smraw[];
    ulonglong2* __restrict__ Wsm = (ulonglong2*)smraw;            // 8*384 = 48 KB
    float*      __restrict__ As  = (float*)(smraw + 8 * G3 * 16); // 2*16*128 = 16 KB

    const float* __restrict__ A = mode ? g_h0 : A_ext;
    float* __restrict__ OUT     = mode ? g_gx1 : g_G0;

    const int j = threadIdx.x;

    // one-time W stage: SMEM part coalesced-ish (4 rows / warp)
    for (int idx = j; idx < G3 * 8; idx += G3) {
        int jj = idx >> 3, q = idx & 7;
        Wsm[q * G3 + jj] = ((const ulonglong2*)(W + jj * HH + 96))[q];
    }
    // reg part: own row (one-time scatter, amortized)
    u64 wreg[48];
    {
        const ulonglong2* __restrict__ Wr = (const ulonglong2*)(W + j * HH);
#pragma unroll
        for (int q = 0; q < 24; q++) {
            ulonglong2 w = Wr[q];
            wreg[2 * q] = w.x; wreg[2 * q + 1] = w.y;
        }
    }
    const float bj = bias[j];

    const int ntiles = (M + GM - 1) / GM;
    int it = blockIdx.x;
    if (it >= ntiles) return;   // uniform across CTA

    // prefetch + stage first tile
    float4 r0 = make_float4(0, 0, 0, 0), r1 = make_float4(0, 0, 0, 0);
    {
        int m = j >> 5, c = j & 31, mm = it * GM + m;
        if (mm < M) r0 = ((const float4*)(A + mm * HH))[c];
        if (j < 128) {
            int m2 = (j + G3) >> 5, c2 = (j + G3) & 31, mm2 = it * GM + m2;
            if (mm2 < M) r1 = ((const float4*)(A + mm2 * HH))[c2];
        }
    }
    ((float4*)As)[j] = r0;
    if (j < 128) ((float4*)As)[j + G3] = r1;
    __syncthreads();

    int buf = 0;
    for (; it < ntiles; it += NCTA, buf ^= 1) {
        const int nxt = it + NCTA;
        // prefetch next tile into regs (latency overlapped with compute)
        if (nxt < ntiles) {
            r0 = make_float4(0, 0, 0, 0); r1 = make_float4(0, 0, 0, 0);
            int m = j >> 5, c = j & 31, mm = nxt * GM + m;
            if (mm < M) r0 = ((const float4*)(A + mm * HH))[c];
            if (j < 128) {
                int m2 = (j + G3) >> 5, c2 = (j + G3) & 31, mm2 = nxt * GM + m2;
                if (mm2 < M) r1 = ((const float4*)(A + mm2 * HH))[c2];
            }
        }

        // compute 16 outputs for column j
        u64 acc[GM];
#pragma unroll
        for (int m = 0; m < GM; m++) acc[m] = 0ull;
        const ulonglong2* __restrict__ At = (const ulonglong2*)(As + (buf ? GM * HH : 0));
#pragma unroll
        for (int q = 0; q < 24; q++) {
            u64 wx = wreg[2 * q], wy = wreg[2 * q + 1];
#pragma unroll
            for (int m = 0; m < GM; m++) {
                ulonglong2 a = At[m * 32 + q];     // broadcast LDS.128
                acc[m] = ffma2(wx, a.x, acc[m]);
                acc[m] = ffma2(wy, a.y, acc[m]);
            }
        }
#pragma unroll
        for (int q = 0; q < 8; q++) {
            ulonglong2 w = Wsm[q * G3 + j];
#pragma unroll
            for (int m = 0; m < GM; m++) {
                ulonglong2 a = At[m * 32 + 24 + q];
                acc[m] = ffma2(w.x, a.x, acc[m]);
                acc[m] = ffma2(w.y, a.y, acc[m]);
            }
        }

        // write outputs (coalesced in j)
        const int m0 = it * GM;
#pragma unroll
        for (int m = 0; m < GM; m++) {
            if (m0 + m < M) {
                float2 s = unpk(acc[m]);
                OUT[(m0 + m) * G3 + j] = bj + s.x + s.y;
            }
        }

        // stage next tile into the other buffer
        if (nxt < ntiles) {
            float* Ad = As + (buf ? 0 : GM * HH);
            ((float4*)Ad)[j] = r0;
            if (j < 128) ((float4*)Ad)[j + G3] = r1;
        }
        __syncthreads();
    }
}

// ---------------------------------------------------------------------------
// Persistent GRU scan. 128 CTAs x 384 threads, 2 batch rows per CTA.
// Thread j computes gate-row j for both batch rows.
// Whh row j: k in [0,96) register-resident (48 u64), k in [96,128) in SMEM.
// ---------------------------------------------------------------------------
__global__ void __launch_bounds__(G3, 1)
gru_scan(const float* __restrict__ Whh, const float* __restrict__ bhh,
         const int* __restrict__ x, int layer)
{
    extern __shared__ ulonglong2 Wsm2[];            // 8*384 ulonglong2 = 48 KB
    __shared__ __align__(16) float hbuf[2][2][HH];  // [buf][row][k]
    __shared__ float2 rp[HH], zp[HH];
    __shared__ int    xs[2][TT];

    const int j  = threadIdx.x;
    const int b0 = blockIdx.x * 2, b1 = b0 + 1;
    const float* __restrict__ gxT = layer ? g_gx1 : g_G0;

    // --- init: W into regs + smem, tokens into smem, h=0 ---
    u64 wreg[48];
    {
        const ulonglong2* __restrict__ Wr = (const ulonglong2*)(Whh + j * HH);
#pragma unroll
        for (int q = 0; q < 24; q++) {              // k = 0..95
            ulonglong2 w = Wr[q];
            wreg[2 * q]     = w.x;
            wreg[2 * q + 1] = w.y;
        }
#pragma unroll
        for (int q = 0; q < 8; q++)                 // k = 96..127
            Wsm2[q * G3 + j] = Wr[24 + q];
    }
    for (int i = j; i < 2 * TT; i += G3) {
        int r = i >> 9, t = i & (TT - 1);
        ((int*)xs)[i] = x[(b0 + r) * TT + t];
    }
    if (j < HH) { hbuf[0][0][j] = 0.0f; hbuf[0][1][j] = 0.0f; }
    const float bh = bhh[j];
    __syncthreads();

    // preload gx for t=0
    float gxa, gxb;
    if (layer == 0) {
        gxa = __ldg(&gxT[xs[0][0] * G3 + j]);
        gxb = __ldg(&gxT[xs[1][0] * G3 + j]);
    } else {
        gxa = __ldg(&gxT[(b0 * TT) * G3 + j]);
        gxb = __ldg(&gxT[(b1 * TT) * G3 + j]);
    }

    for (int t = 0; t < TT; t++) {
        const int buf = t & 1;

        // prefetch next step's input gates
        float ngxa = 0.0f, ngxb = 0.0f;
        if (t + 1 < TT) {
            if (layer == 0) {
                ngxa = __ldg(&gxT[xs[0][t + 1] * G3 + j]);
                ngxb = __ldg(&gxT[xs[1][t + 1] * G3 + j]);
            } else {
                ngxa = __ldg(&gxT[(b0 * TT + t + 1) * G3 + j]);
                ngxb = __ldg(&gxT[(b1 * TT + t + 1) * G3 + j]);
            }
        }

        // gh[j] for both rows: packed k-pair dot product
        u64 a0 = 0ull, a1 = 0ull, a2 = 0ull, a3 = 0ull;
        const ulonglong2* __restrict__ h0p = (const ulonglong2*)hbuf[buf][0];
        const ulonglong2* __restrict__ h1p = (const ulonglong2*)hbuf[buf][1];
#pragma unroll
        for (int q = 0; q < 24; q++) {
            ulonglong2 ha = h0p[q];
            ulonglong2 hb = h1p[q];
            a0 = ffma2(wreg[2 * q],     ha.x, a0);
            a1 = ffma2(wreg[2 * q + 1], ha.y, a1);
            a2 = ffma2(wreg[2 * q],     hb.x, a2);
            a3 = ffma2(wreg[2 * q + 1], hb.y, a3);
        }
#pragma unroll
        for (int q = 0; q < 8; q++) {
            ulonglong2 w  = Wsm2[q * G3 + j];
            ulonglong2 ha = h0p[24 + q];
            ulonglong2 hb = h1p[24 + q];
            a0 = ffma2(w.x, ha.x, a0);
            a1 = ffma2(w.y, ha.y, a1);
            a2 = ffma2(w.x, hb.x, a2);
            a3 = ffma2(w.y, hb.y, a3);
        }
        float2 f0 = unpk(a0), f1 = unpk(a1), f2 = unpk(a2), f3 = unpk(a3);
        float gh0 = bh + ((f0.x + f0.y) + (f1.x + f1.y));
        float gh1 = bh + ((f2.x + f2.y) + (f3.x + f3.y));

        // gate split: warps 0-3 -> r, 4-7 -> z, 8-11 -> n + state update
        if (j < HH) {
            rp[j] = make_float2(sigf(gxa + gh0), sigf(gxb + gh1));
        } else if (j < 2 * HH) {
            zp[j - HH] = make_float2(sigf(gxa + gh0), sigf(gxb + gh1));
        }
        __syncthreads();
        if (j >= 2 * HH) {
            const int i = j - 2 * HH;
            float2 r = rp[i], z = zp[i];
            float n0 = tanhfast(gxa + r.x * gh0);
            float n1 = tanhfast(gxb + r.y * gh1);
            float h0o = hbuf[buf][0][i], h1o = hbuf[buf][1][i];
            float hn0 = n0 + z.x * (h0o - n0);     // (1-z)*n + z*h
            float hn1 = n1 + z.y * (h1o - n1);
            hbuf[buf ^ 1][0][i] = hn0;
            hbuf[buf ^ 1][1][i] = hn1;
            if (layer == 0) {
                g_h0[(b0 * TT + t) * HH + i] = hn0;
                g_h0[(b1 * TT + t) * HH + i] = hn1;
            } else if (t == TT - 1) {
                g_hlast[b0 * HH + i] = hn0;
                g_hlast[b1 * HH + i] = hn1;
            }
        }
        __syncthreads();
        gxa = ngxa;
        gxb = ngxb;
    }
}

// ---------------------------------------------------------------------------
// out[b, o] = fc_b[o] + sum_k relu(hlast[b,k]) * fc_w[o,k]
// ---------------------------------------------------------------------------
__global__ void __launch_bounds__(BB)
fc_kernel(const float* __restrict__ fcw, const float* __restrict__ fcb,
          float* __restrict__ out)
{
    __shared__ float ws[3 * HH];
    int b = threadIdx.x;
    for (int i = b; i < 3 * HH; i += BB) ws[i] = fcw[i];
    __syncthreads();
    float a0 = fcb[0], a1 = fcb[1], a2 = fcb[2];
#pragma unroll 4
    for (int k = 0; k < HH; k++) {
        float h = g_hlast[b * HH + k];
        h = h > 0.0f ? h : 0.0f;
        a0 = fmaf(h, ws[k], a0);
        a1 = fmaf(h, ws[HH + k], a1);
        a2 = fmaf(h, ws[2 * HH + k], a2);
    }
    out[b * 3 + 0] = a0;
    out[b * 3 + 1] = a1;
    out[b * 3 + 2] = a2;
}

// ---------------------------------------------------------------------------
extern "C" void kernel_launch(void* const* d_in, const int* in_sizes, int n_in,
                              void* d_out, int out_size)
{
    const int*   x    = (const int*)  d_in[0];
    const float* emb  = (const float*)d_in[1];
    const float* W_ih = (const float*)d_in[2];   // [2][384][128]
    const float* W_hh = (const float*)d_in[3];   // [2][384][128]
    const float* b_ih = (const float*)d_in[4];   // [2][384]
    const float* b_hh = (const float*)d_in[5];   // [2][384]
    const float* fc_w = (const float*)d_in[6];   // [3][128]
    const float* fc_b = (const float*)d_in[7];   // [3]
    float* out = (float*)d_out;

    const int smem_scan = 8 * G3 * (int)sizeof(ulonglong2);          // 48 KB
    const int smem_gemm = smem_scan + 2 * GM * HH * (int)sizeof(float); // 64 KB
    cudaFuncSetAttribute(gru_scan, cudaFuncAttributeMaxDynamicSharedMemorySize,
                         smem_scan);
    cudaFuncSetAttribute(gemm_persist, cudaFuncAttributeMaxDynamicSharedMemorySize,
                         smem_gemm);

    // 1) G0 = emb @ Wih0^T + b_ih0  (vocab-side precompute: V < B*T)
    gemm_persist<<<NCTA, G3, smem_gemm>>>(emb, W_ih, b_ih, VV, 0);
    // 2) layer-0 scan (gx gathered from G0), writes g_h0
    gru_scan<<<BB / 2, G3, smem_scan>>>(W_hh, b_hh, x, 0);
    // 3) gx1 = h0 @ Wih1^T + b_ih1
    gemm_persist<<<NCTA, G3, smem_gemm>>>(nullptr, W_ih + G3 * HH, b_ih + G3, BB * TT, 1);
    // 4) layer-1 scan, writes g_hlast
    gru_scan<<<BB / 2, G3, smem_scan>>>(W_hh + G3 * HH, b_hh + G3, x, 1);
    // 5) head
    fc_kernel<<<1, BB>>>(fc_w, fc_b, out);
}

// round 4
// speedup vs baseline: 1.4590x; 1.0243x over previous
#include <cuda_runtime.h>
#include <math.h>

typedef unsigned long long u64;

// Problem constants
#define BB 256
#define TT 512
#define HH 128
#define VV 29275
#define G3 384          // 3*H
#define GM 16           // gemm row tile
#define NCTA 148        // persistent gemm grid

// Scratch (static device globals — no runtime allocation)
__device__ float g_G0[VV * G3];        // emb @ Wih0^T + b_ih0   (~45 MB)
__device__ float g_h0[BB * TT * HH];   // layer-0 hidden outputs (~64 MB)
__device__ float g_gx1[BB * TT * G3];  // h0 @ Wih1^T + b_ih1    (~201 MB)
__device__ float g_hlast[BB * HH];     // layer-1 final hidden

// ---------------------------------------------------------------------------
// f32x2 packed helpers
// ---------------------------------------------------------------------------
__device__ __forceinline__ u64 ffma2(u64 a, u64 b, u64 c) {
    u64 d;
    asm("fma.rn.f32x2 %0, %1, %2, %3;" : "=l"(d) : "l"(a), "l"(b), "l"(c));
    return d;
}
__device__ __forceinline__ float2 unpk(u64 v) {
    float2 r;
    asm("mov.b64 {%0, %1}, %2;" : "=f"(r.x), "=f"(r.y) : "l"(v));
    return r;
}

// single-MUFU activations
__device__ __forceinline__ float mtanh(float v) {
    float r;
    asm("tanh.approx.f32 %0, %1;" : "=f"(r) : "f"(v));
    return r;
}
__device__ __forceinline__ float msig(float v) {
    return fmaf(0.5f, mtanh(0.5f * v), 0.5f);
}

// ---------------------------------------------------------------------------
// Persistent GEMM: OUT[m, j] = bias[j] + sum_k A[m,k] * W[j,k]
// (unchanged from R3 — near its crossbar/fma floor)
// ---------------------------------------------------------------------------
__global__ void __launch_bounds__(G3, 1)
gemm_persist(const float* __restrict__ A_ext, const float* __restrict__ W,
             const float* __restrict__ bias, int M, int mode)
{
    extern __shared__ char smraw[];
    ulonglong2* __restrict__ Wsm = (ulonglong2*)smraw;            // 48 KB
    float*      __restrict__ As  = (float*)(smraw + 8 * G3 * 16); // 16 KB

    const float* __restrict__ A = mode ? g_h0 : A_ext;
    float* __restrict__ OUT     = mode ? g_gx1 : g_G0;

    const int j = threadIdx.x;

    for (int idx = j; idx < G3 * 8; idx += G3) {
        int jj = idx >> 3, q = idx & 7;
        Wsm[q * G3 + jj] = ((const ulonglong2*)(W + jj * HH + 96))[q];
    }
    u64 wreg[48];
    {
        const ulonglong2* __restrict__ Wr = (const ulonglong2*)(W + j * HH);
#pragma unroll
        for (int q = 0; q < 24; q++) {
            ulonglong2 w = Wr[q];
            wreg[2 * q] = w.x; wreg[2 * q + 1] = w.y;
        }
    }
    const float bj = bias[j];

    const int ntiles = (M + GM - 1) / GM;
    int it = blockIdx.x;
    if (it >= ntiles) return;

    float4 r0 = make_float4(0, 0, 0, 0), r1 = make_float4(0, 0, 0, 0);
    {
        int m = j >> 5, c = j & 31, mm = it * GM + m;
        if (mm < M) r0 = ((const float4*)(A + mm * HH))[c];
        if (j < 128) {
            int m2 = (j + G3) >> 5, c2 = (j + G3) & 31, mm2 = it * GM + m2;
            if (mm2 < M) r1 = ((const float4*)(A + mm2 * HH))[c2];
        }
    }
    ((float4*)As)[j] = r0;
    if (j < 128) ((float4*)As)[j + G3] = r1;
    __syncthreads();

    int buf = 0;
    for (; it < ntiles; it += NCTA, buf ^= 1) {
        const int nxt = it + NCTA;
        if (nxt < ntiles) {
            r0 = make_float4(0, 0, 0, 0); r1 = make_float4(0, 0, 0, 0);
            int m = j >> 5, c = j & 31, mm = nxt * GM + m;
            if (mm < M) r0 = ((const float4*)(A + mm * HH))[c];
            if (j < 128) {
                int m2 = (j + G3) >> 5, c2 = (j + G3) & 31, mm2 = nxt * GM + m2;
                if (mm2 < M) r1 = ((const float4*)(A + mm2 * HH))[c2];
            }
        }

        u64 acc[GM];
#pragma unroll
        for (int m = 0; m < GM; m++) acc[m] = 0ull;
        const ulonglong2* __restrict__ At = (const ulonglong2*)(As + (buf ? GM * HH : 0));
#pragma unroll
        for (int q = 0; q < 24; q++) {
            u64 wx = wreg[2 * q], wy = wreg[2 * q + 1];
#pragma unroll
            for (int m = 0; m < GM; m++) {
                ulonglong2 a = At[m * 32 + q];
                acc[m] = ffma2(wx, a.x, acc[m]);
                acc[m] = ffma2(wy, a.y, acc[m]);
            }
        }
#pragma unroll
        for (int q = 0; q < 8; q++) {
            ulonglong2 w = Wsm[q * G3 + j];
#pragma unroll
            for (int m = 0; m < GM; m++) {
                ulonglong2 a = At[m * 32 + 24 + q];
                acc[m] = ffma2(w.x, a.x, acc[m]);
                acc[m] = ffma2(w.y, a.y, acc[m]);
            }
        }

        const int m0 = it * GM;
#pragma unroll
        for (int m = 0; m < GM; m++) {
            if (m0 + m < M) {
                float2 s = unpk(acc[m]);
                OUT[(m0 + m) * G3 + j] = bj + s.x + s.y;
            }
        }

        if (nxt < ntiles) {
            float* Ad = As + (buf ? 0 : GM * HH);
            ((float4*)Ad)[j] = r0;
            if (j < 128) ((float4*)Ad)[j + G3] = r1;
        }
        __syncthreads();
    }
}

// ---------------------------------------------------------------------------
// Persistent GRU scan. 128 CTAs x 384 threads, 2 batch rows per CTA.
// R4: tanh.approx gates, named-barrier arrive/sync for the r/z -> n handoff,
// old-h hoisted above the handoff barrier.
// ---------------------------------------------------------------------------
__global__ void __launch_bounds__(G3, 1)
gru_scan(const float* __restrict__ Whh, const float* __restrict__ bhh,
         const int* __restrict__ x, int layer)
{
    extern __shared__ ulonglong2 Wsm2[];            // 8*384 ulonglong2 = 48 KB
    __shared__ __align__(16) float hbuf[2][2][HH];  // [buf][row][k]
    __shared__ float2 rp[HH], zp[HH];
    __shared__ int    xs[2][TT];

    const int j  = threadIdx.x;
    const int b0 = blockIdx.x * 2, b1 = b0 + 1;
    const float* __restrict__ gxT = layer ? g_gx1 : g_G0;

    // --- init ---
    u64 wreg[48];
    {
        const ulonglong2* __restrict__ Wr = (const ulonglong2*)(Whh + j * HH);
#pragma unroll
        for (int q = 0; q < 24; q++) {
            ulonglong2 w = Wr[q];
            wreg[2 * q]     = w.x;
            wreg[2 * q + 1] = w.y;
        }
#pragma unroll
        for (int q = 0; q < 8; q++)
            Wsm2[q * G3 + j] = Wr[24 + q];
    }
    for (int i = j; i < 2 * TT; i += G3) {
        int r = i >> 9, t = i & (TT - 1);
        ((int*)xs)[i] = x[(b0 + r) * TT + t];
    }
    if (j < HH) { hbuf[0][0][j] = 0.0f; hbuf[0][1][j] = 0.0f; }
    const float bh = bhh[j];
    __syncthreads();

    float gxa, gxb;
    if (layer == 0) {
        gxa = __ldg(&gxT[xs[0][0] * G3 + j]);
        gxb = __ldg(&gxT[xs[1][0] * G3 + j]);
    } else {
        gxa = __ldg(&gxT[(b0 * TT) * G3 + j]);
        gxb = __ldg(&gxT[(b1 * TT) * G3 + j]);
    }

    for (int t = 0; t < TT; t++) {
        const int buf = t & 1;

        // prefetch next step's input gates
        float ngxa = 0.0f, ngxb = 0.0f;
        if (t + 1 < TT) {
            if (layer == 0) {
                ngxa = __ldg(&gxT[xs[0][t + 1] * G3 + j]);
                ngxb = __ldg(&gxT[xs[1][t + 1] * G3 + j]);
            } else {
                ngxa = __ldg(&gxT[(b0 * TT + t + 1) * G3 + j]);
                ngxb = __ldg(&gxT[(b1 * TT + t + 1) * G3 + j]);
            }
        }

        // gh[j] for both rows: packed k-pair dot product
        u64 a0 = 0ull, a1 = 0ull, a2 = 0ull, a3 = 0ull;
        const ulonglong2* __restrict__ h0p = (const ulonglong2*)hbuf[buf][0];
        const ulonglong2* __restrict__ h1p = (const ulonglong2*)hbuf[buf][1];
#pragma unroll
        for (int q = 0; q < 24; q++) {
            ulonglong2 ha = h0p[q];
            ulonglong2 hb = h1p[q];
            a0 = ffma2(wreg[2 * q],     ha.x, a0);
            a1 = ffma2(wreg[2 * q + 1], ha.y, a1);
            a2 = ffma2(wreg[2 * q],     hb.x, a2);
            a3 = ffma2(wreg[2 * q + 1], hb.y, a3);
        }
#pragma unroll
        for (int q = 0; q < 8; q++) {
            ulonglong2 w  = Wsm2[q * G3 + j];
            ulonglong2 ha = h0p[24 + q];
            ulonglong2 hb = h1p[24 + q];
            a0 = ffma2(w.x, ha.x, a0);
            a1 = ffma2(w.y, ha.y, a1);
            a2 = ffma2(w.x, hb.x, a2);
            a3 = ffma2(w.y, hb.y, a3);
        }
        float2 f0 = unpk(a0), f1 = unpk(a1), f2 = unpk(a2), f3 = unpk(a3);
        float gh0 = bh + ((f0.x + f0.y) + (f1.x + f1.y));
        float gh1 = bh + ((f2.x + f2.y) + (f3.x + f3.y));

        // gate split: warps 0-3 -> r, 4-7 -> z (producers, non-blocking arrive);
        // warps 8-11 -> n + state update (consumers).
        if (j < 2 * HH) {
            if (j < HH) {
                rp[j] = make_float2(msig(gxa + gh0), msig(gxb + gh1));
            } else {
                zp[j - HH] = make_float2(msig(gxa + gh0), msig(gxb + gh1));
            }
            asm volatile("bar.arrive 1, %0;" :: "n"(G3) : "memory");
        } else {
            const int i = j - 2 * HH;
            // old h: stable since last step -> read before the handoff barrier
            float h0o = hbuf[buf][0][i], h1o = hbuf[buf][1][i];
            asm volatile("bar.sync 1, %0;" :: "n"(G3) : "memory");
            float2 r = rp[i], z = zp[i];
            float n0 = mtanh(gxa + r.x * gh0);
            float n1 = mtanh(gxb + r.y * gh1);
            float hn0 = n0 + z.x * (h0o - n0);     // (1-z)*n + z*h
            float hn1 = n1 + z.y * (h1o - n1);
            hbuf[buf ^ 1][0][i] = hn0;
            hbuf[buf ^ 1][1][i] = hn1;
            if (layer == 0) {
                g_h0[(b0 * TT + t) * HH + i] = hn0;
                g_h0[(b1 * TT + t) * HH + i] = hn1;
            } else if (t == TT - 1) {
                g_hlast[b0 * HH + i] = hn0;
                g_hlast[b1 * HH + i] = hn1;
            }
        }
        __syncthreads();
        gxa = ngxa;
        gxb = ngxb;
    }
}

// ---------------------------------------------------------------------------
__global__ void __launch_bounds__(BB)
fc_kernel(const float* __restrict__ fcw, const float* __restrict__ fcb,
          float* __restrict__ out)
{
    __shared__ float ws[3 * HH];
    int b = threadIdx.x;
    for (int i = b; i < 3 * HH; i += BB) ws[i] = fcw[i];
    __syncthreads();
    float a0 = fcb[0], a1 = fcb[1], a2 = fcb[2];
#pragma unroll 4
    for (int k = 0; k < HH; k++) {
        float h = g_hlast[b * HH + k];
        h = h > 0.0f ? h : 0.0f;
        a0 = fmaf(h, ws[k], a0);
        a1 = fmaf(h, ws[HH + k], a1);
        a2 = fmaf(h, ws[2 * HH + k], a2);
    }
    out[b * 3 + 0] = a0;
    out[b * 3 + 1] = a1;
    out[b * 3 + 2] = a2;
}

// ---------------------------------------------------------------------------
extern "C" void kernel_launch(void* const* d_in, const int* in_sizes, int n_in,
                              void* d_out, int out_size)
{
    const int*   x    = (const int*)  d_in[0];
    const float* emb  = (const float*)d_in[1];
    const float* W_ih = (const float*)d_in[2];   // [2][384][128]
    const float* W_hh = (const float*)d_in[3];   // [2][384][128]
    const float* b_ih = (const float*)d_in[4];   // [2][384]
    const float* b_hh = (const float*)d_in[5];   // [2][384]
    const float* fc_w = (const float*)d_in[6];   // [3][128]
    const float* fc_b = (const float*)d_in[7];   // [3]
    float* out = (float*)d_out;

    const int smem_scan = 8 * G3 * (int)sizeof(ulonglong2);             // 48 KB
    const int smem_gemm = smem_scan + 2 * GM * HH * (int)sizeof(float); // 64 KB
    cudaFuncSetAttribute(gru_scan, cudaFuncAttributeMaxDynamicSharedMemorySize,
                         smem_scan);
    cudaFuncSetAttribute(gemm_persist, cudaFuncAttributeMaxDynamicSharedMemorySize,
                         smem_gemm);

    // 1) G0 = emb @ Wih0^T + b_ih0  (vocab-side precompute: V < B*T)
    gemm_persist<<<NCTA, G3, smem_gemm>>>(emb, W_ih, b_ih, VV, 0);
    // 2) layer-0 scan (gx gathered from G0), writes g_h0
    gru_scan<<<BB / 2, G3, smem_scan>>>(W_hh, b_hh, x, 0);
    // 3) gx1 = h0 @ Wih1^T + b_ih1
    gemm_persist<<<NCTA, G3, smem_gemm>>>(nullptr, W_ih + G3 * HH, b_ih + G3, BB * TT, 1);
    // 4) layer-1 scan, writes g_hlast
    gru_scan<<<BB / 2, G3, smem_scan>>>(W_hh + G3 * HH, b_hh + G3, x, 1);
    // 5) head
    fc_kernel<<<1, BB>>>(fc_w, fc_b, out);
}